// round 9
// baseline (speedup 1.0000x reference)
#include <cuda_runtime.h>
#include <cuda_bf16.h>
#include <cstdint>

#define BQ    1024
#define QMAX  32768
#define DIM   256
#define PERP  15
#define CANDMAX 256
#define DELTA 8.0f
#define QSCALE 20.0f            // int8 quant scale
#define INV_S2 (1.0f/200.0f)    // 2 / (QSCALE*QSCALE)
#define CAP   2048              // per-row candidate list capacity
#define TAU_Z 2.5f              // threshold: mean - 2.5 sigma (~200 pass / row)

// ---------------- scratch ----------------------------------------------------
__device__ __align__(16) int8_t g_q8[(size_t)QMAX * DIM];      // int8 mirror (8 MB)
__device__ float g_y2[QMAX];
__device__ unsigned long long g_cand[(size_t)BQ * CAP];        // 16 MB candidate lists
__device__ int   g_cnt[BQ];

// ---------------- prep: int8 quant + norms + cnt reset -----------------------
__global__ void __launch_bounds__(256) prep_kernel(const float* __restrict__ data,
                                                   const float* __restrict__ queue) {
    const int t    = threadIdx.x;
    const int row  = blockIdx.x * 4 + (t >> 6);
    const int l    = t & 63;
    const float* src = (row < BQ) ? (data + (size_t)row * DIM)
                                  : (queue + (size_t)(row - BQ) * DIM);
    float4 v = *(const float4*)(src + l * 4);

    int q0 = __float2int_rn(fminf(fmaxf(v.x * QSCALE, -127.f), 127.f));
    int q1 = __float2int_rn(fminf(fmaxf(v.y * QSCALE, -127.f), 127.f));
    int q2 = __float2int_rn(fminf(fmaxf(v.z * QSCALE, -127.f), 127.f));
    int q3 = __float2int_rn(fminf(fmaxf(v.w * QSCALE, -127.f), 127.f));
    uint32_t packed = (uint32_t)(q0 & 0xff) | ((uint32_t)(q1 & 0xff) << 8) |
                      ((uint32_t)(q2 & 0xff) << 16) | ((uint32_t)(q3 & 0xff) << 24);
    *(uint32_t*)(&g_q8[(size_t)row * DIM + l * 4]) = packed;

    float s = v.x*v.x + v.y*v.y + v.z*v.z + v.w*v.w;
    #pragma unroll
    for (int o = 16; o; o >>= 1) s += __shfl_xor_sync(0xffffffffu, s, o);
    __shared__ float ws[8];
    if ((t & 31) == 0) ws[t >> 5] = s;
    __syncthreads();
    if (l == 0) {
        g_y2[row] = ws[(t >> 6) * 2] + ws[(t >> 6) * 2 + 1];
        if (row < BQ) g_cnt[row] = 0;
    }
}

// ---------------- persistent int8 IMMA GEMM, single wave ----------------------
// Grid 8(M) x 32(N-groups). CTA: A[128 x 256] resident; sweeps 8 N-tiles of 128
// through a 4-stage cp.async B ring (chunks of 128 rows x 64B). One sync/chunk.
#define A_STR   272                          // A row stride bytes (conflict-free)
#define A_SZ    (128 * A_STR)                // 34816
#define B_STR   80
#define B_STAGE (128 * B_STR)                // 10240
#define OFF_A   0
#define OFF_B   A_SZ
#define OFF_Y2  (OFF_B + 4 * B_STAGE)        // 75776 : 1024 floats (8 tiles x 128)
#define OFF_TAU (OFF_Y2 + 1024 * 4)          // 79872 : 128 floats
#define GSMEM   (OFF_TAU + 128 * 4)          // 80384

__device__ __forceinline__ uint32_t smem_u32(const void* p) {
    uint32_t a;
    asm("{ .reg .u64 t; cvta.to.shared.u64 t, %1; cvt.u32.u64 %0, t; }" : "=r"(a) : "l"(p));
    return a;
}
#define CP_ASYNC16(dst, src) \
    asm volatile("cp.async.cg.shared.global [%0], [%1], 16;" :: "r"(dst), "l"(src))
#define CP_COMMIT() asm volatile("cp.async.commit_group;" ::: "memory")
#define CP_WAIT(n)  asm volatile("cp.async.wait_group %0;" :: "n"(n) : "memory")

__device__ __forceinline__ void ldsm_x4(uint32_t& r0, uint32_t& r1, uint32_t& r2,
                                        uint32_t& r3, uint32_t addr) {
    asm volatile("ldmatrix.sync.aligned.m8n8.x4.shared.b16 {%0,%1,%2,%3}, [%4];"
                 : "=r"(r0), "=r"(r1), "=r"(r2), "=r"(r3) : "r"(addr));
}
__device__ __forceinline__ void mma_s8(int c[4], uint32_t a0, uint32_t a1,
                                       uint32_t a2, uint32_t a3,
                                       uint32_t b0, uint32_t b1) {
    asm volatile(
        "mma.sync.aligned.m16n8k32.row.col.s32.s8.s8.s32 "
        "{%0,%1,%2,%3}, {%4,%5,%6,%7}, {%8,%9}, {%0,%1,%2,%3};\n"
        : "+r"(c[0]), "+r"(c[1]), "+r"(c[2]), "+r"(c[3])
        : "r"(a0), "r"(a1), "r"(a2), "r"(a3), "r"(b0), "r"(b1));
}
__device__ __forceinline__ unsigned long long make_key(float v, int j) {
    unsigned u = __float_as_uint(v);
    u = (u & 0x80000000u) ? ~u : (u | 0x80000000u);
    return ((unsigned long long)u << 32) | (unsigned)j;
}
__device__ __forceinline__ float key_val(unsigned long long k) {
    unsigned s = (unsigned)(k >> 32);
    unsigned u = (s & 0x80000000u) ? (s ^ 0x80000000u) : ~s;
    return __uint_as_float(u);
}
__device__ __forceinline__ void emit_cand(float v, int ri, int cj, float tau) {
    if (v < tau && cj != ri) {
        int p = atomicAdd(&g_cnt[ri], 1);
        if (p < CAP) g_cand[(size_t)ri * CAP + p] = make_key(v, cj);
    }
}

__global__ void __launch_bounds__(256, 2) gemm_kernel() {
    extern __shared__ __align__(16) char smem[];
    const uint32_t sb = smem_u32(smem);
    float* sy2  = (float*)(smem + OFF_Y2);
    float* stau = (float*)(smem + OFF_TAU);

    const int t    = threadIdx.x;
    const int lane = t & 31, wid = t >> 5;
    const int bm   = blockIdx.y * 128;           // M tile
    const int ng   = blockIdx.x * 8;             // first N tile of this CTA
    const int wm   = (wid >> 2) * 64;            // 0,64
    const int wn   = (wid & 3) * 32;             // 0..96
    const int gid  = lane >> 2, tig = lane & 3;

    // y2 for all 8 N tiles (1024 floats) + per-row tau
    *(float4*)&sy2[t * 4] = *(const float4*)&g_y2[ng * 128 + t * 4];
    if (t < 128) {
        const float x2 = g_y2[bm + t];
        stau[t] = 256.0f - TAU_Z * sqrtf(fmaf(4.0f, x2, 512.0f));
    }

    // A: 128 rows x 256B, resident (2048 x 16B chunks)
    #pragma unroll
    for (int i = t; i < 2048; i += 256) {
        const int r = i >> 4, c = i & 15;
        CP_ASYNC16(sb + OFF_A + (uint32_t)(r * A_STR + c * 16),
                   (const char*)&g_q8[(size_t)(bm + r) * DIM + c * 16]);
    }
    CP_COMMIT();

    // B chunk j (j = tile*4 + kc): 128 rows x 64B into stage j%4
    auto issueB = [&](int j) {
        const int bn = (ng + (j >> 2)) * 128;
        const int kc = j & 3;
        const uint32_t bbuf = sb + OFF_B + (uint32_t)(j & 3) * B_STAGE;
        #pragma unroll
        for (int x = t; x < 512; x += 256) {
            const int r = x >> 2, c = x & 3;
            CP_ASYNC16(bbuf + (uint32_t)(r * B_STR + c * 16),
                       (const char*)&g_q8[(size_t)(bn + r) * DIM + kc * 64 + c * 16]);
        }
    };
    issueB(0); CP_COMMIT();
    issueB(1); CP_COMMIT();
    issueB(2); CP_COMMIT();

    int acc[4][4][4];
    #pragma unroll
    for (int mi = 0; mi < 4; mi++)
        #pragma unroll
        for (int ni = 0; ni < 4; ni++)
            #pragma unroll
            for (int e = 0; e < 4; e++) acc[mi][ni][e] = 0;

    for (int i = 0; i < 32; i++) {
        CP_WAIT(2);
        __syncthreads();                          // chunk i visible; stage (i+3)%4 free
        if (i + 3 < 32) issueB(i + 3);
        CP_COMMIT();

        const int kc = i & 3;
        const uint32_t bbuf = sb + OFF_B + (uint32_t)(i & 3) * B_STAGE;
        #pragma unroll
        for (int kk = 0; kk < 64; kk += 32) {
            uint32_t a[4][4], b[4][2];
            const int acol = kc * 64 + kk + ((lane >> 4) << 4);
            #pragma unroll
            for (int mi = 0; mi < 4; mi++) {
                const int ar = wm + mi * 16 + (lane & 15);
                ldsm_x4(a[mi][0], a[mi][1], a[mi][2], a[mi][3],
                        sb + OFF_A + (uint32_t)(ar * A_STR + acol));
            }
            const int bcol = kk + (((lane >> 3) & 1) << 4);
            #pragma unroll
            for (int nj = 0; nj < 4; nj += 2) {
                const int br = wn + nj * 8 + (lane & 7) + ((lane >> 4) << 3);
                ldsm_x4(b[nj][0], b[nj][1], b[nj + 1][0], b[nj + 1][1],
                        bbuf + (uint32_t)(br * B_STR + bcol));
            }
            #pragma unroll
            for (int mi = 0; mi < 4; mi++)
                #pragma unroll
                for (int ni = 0; ni < 4; ni++)
                    mma_s8(acc[mi][ni], a[mi][0], a[mi][1], a[mi][2], a[mi][3],
                           b[ni][0], b[ni][1]);
        }

        if (kc == 3) {                            // N-tile finished: filter + emit
            const int nl = i >> 2;
            const int bn = (ng + nl) * 128;
            #pragma unroll
            for (int mi = 0; mi < 4; mi++) {
                const int lr = wm + mi * 16 + gid;
                const float tau0 = stau[lr], tau1 = stau[lr + 8];
                #pragma unroll
                for (int ni = 0; ni < 4; ni++) {
                    const int lc = wn + ni * 8 + tig * 2;
                    const float y0 = sy2[nl * 128 + lc], y1 = sy2[nl * 128 + lc + 1];
                    emit_cand(fmaf(-INV_S2, (float)acc[mi][ni][0], y0), bm + lr,     bn + lc,     tau0);
                    emit_cand(fmaf(-INV_S2, (float)acc[mi][ni][1], y1), bm + lr,     bn + lc + 1, tau0);
                    emit_cand(fmaf(-INV_S2, (float)acc[mi][ni][2], y0), bm + lr + 8, bn + lc,     tau1);
                    emit_cand(fmaf(-INV_S2, (float)acc[mi][ni][3], y1), bm + lr + 8, bn + lc + 1, tau1);
                    #pragma unroll
                    for (int e = 0; e < 4; e++) acc[mi][ni][e] = 0;
                }
            }
        }
    }
}

// ---------------- select: candidate list -> approx top-15 -> exact -----------
__global__ void __launch_bounds__(256) select_kernel(const float* __restrict__ data,
                                                     const float* __restrict__ queue,
                                                     const int* __restrict__ jdx,
                                                     float* __restrict__ out) {
    __shared__ unsigned long long skeys[256 * PERP];
    __shared__ unsigned long long swarp[8];
    __shared__ unsigned long long s_bcast;
    __shared__ unsigned long long sx[PERP];
    __shared__ __align__(16) float sdata[DIM];
    __shared__ int   cand[CANDMAX];
    __shared__ unsigned long long ckeys[CANDMAX];
    __shared__ int   s_cnt, s_nbr;

    const int row = blockIdx.x;
    const int t   = threadIdx.x;
    const int cnt0 = min(g_cnt[row], CAP);
    const unsigned long long* crow = g_cand + (size_t)row * CAP;

    if (t == 0) s_cnt = PERP;
    sdata[t] = data[(size_t)row * DIM + t];

    unsigned long long keys[PERP];
    #pragma unroll
    for (int i = 0; i < PERP; i++) keys[i] = ~0ULL;
    for (int j = t; j < cnt0; j += 256) {
        unsigned long long key = crow[j];
        if (key < keys[PERP - 1]) {
            #pragma unroll
            for (int i = PERP - 1; i >= 1; i--) {
                unsigned long long up = keys[i - 1];
                keys[i] = (key < up) ? up : ((key < keys[i]) ? key : keys[i]);
            }
            keys[0] = (key < keys[0]) ? key : keys[0];
        }
    }
    #pragma unroll
    for (int i = 0; i < PERP; i++) skeys[t * PERP + i] = keys[i];
    __syncthreads();

    for (int it = 0; it < PERP; it++) {
        unsigned long long m = ~0ULL;
        #pragma unroll
        for (int i = 0; i < PERP; i++) {
            unsigned long long v = skeys[t + i * 256];
            m = (v < m) ? v : m;
        }
        #pragma unroll
        for (int o = 16; o; o >>= 1) {
            unsigned long long other = __shfl_xor_sync(0xffffffffu, m, o);
            m = (other < m) ? other : m;
        }
        if ((t & 31) == 0) swarp[t >> 5] = m;
        __syncthreads();
        if (t == 0) {
            unsigned long long mm = swarp[0];
            #pragma unroll
            for (int i = 1; i < 8; i++) mm = (swarp[i] < mm) ? swarp[i] : mm;
            s_bcast = mm;
            sx[it]  = mm;
        }
        __syncthreads();
        unsigned long long cur = s_bcast;
        #pragma unroll
        for (int i = 0; i < PERP; i++) {
            int idx = t + i * 256;
            if (skeys[idx] == cur) skeys[idx] = ~0ULL;
        }
        __syncthreads();
    }

    const unsigned long long tkey = make_key(key_val(sx[PERP - 1]) + DELTA, 0);
    if (t < PERP) cand[t] = (int)(sx[t] & 0xffffffffu);
    #pragma unroll
    for (int i = 0; i < PERP; i++) {
        unsigned long long v = skeys[t + i * 256];
        if (v < tkey) {
            int p = atomicAdd(&s_cnt, 1);
            if (p < CANDMAX) cand[p] = (int)(v & 0xffffffffu);
        }
    }
    __syncthreads();
    const int cnt = (s_cnt < CANDMAX) ? s_cnt : CANDMAX;

    {
        const int lane = t & 31, wid = t >> 5;
        for (int c = wid; c < cnt; c += 8) {
            const int j = cand[c];
            const float* qj = (j < BQ) ? (data + (size_t)j * DIM)
                                       : (queue + (size_t)(j - BQ) * DIM);
            float4 x0 = *(const float4*)&sdata[lane * 8];
            float4 x1 = *(const float4*)&sdata[lane * 8 + 4];
            float4 y0 = *(const float4*)&qj[lane * 8];
            float4 y1 = *(const float4*)&qj[lane * 8 + 4];
            float d = x0.x*y0.x + x0.y*y0.y + x0.z*y0.z + x0.w*y0.w
                    + x1.x*y1.x + x1.y*y1.y + x1.z*y1.z + x1.w*y1.w;
            #pragma unroll
            for (int o = 16; o; o >>= 1) d += __shfl_xor_sync(0xffffffffu, d, o);
            if (lane == 0) ckeys[c] = make_key(fmaf(-2.0f, d, g_y2[j]), j);
        }
    }
    __syncthreads();

    const int r = jdx[row];
    if (t < cnt) {
        unsigned long long mykey = ckeys[t];
        int rank = 0;
        for (int d = 0; d < cnt; d++) rank += (ckeys[d] < mykey);
        if (rank == r) s_nbr = cand[t];
    }
    __syncthreads();
    const int nbr = s_nbr;
    const float* srow = (nbr < BQ) ? (data + (size_t)nbr * DIM)
                                   : (queue + (size_t)(nbr - BQ) * DIM);
    out[(size_t)row * DIM + t] = srow[t];
}

// ---------------- launch -----------------------------------------------------
extern "C" void kernel_launch(void* const* d_in, const int* in_sizes, int n_in,
                              void* d_out, int out_size) {
    (void)in_sizes; (void)n_in; (void)out_size;
    const float* data  = (const float*)d_in[0];
    const float* queue = (const float*)d_in[1];
    const int*   jdx   = (const int*)d_in[2];
    float*       out   = (float*)d_out;

    cudaFuncSetAttribute(gemm_kernel, cudaFuncAttributeMaxDynamicSharedMemorySize, GSMEM);

    prep_kernel<<<QMAX / 4, 256>>>(data, queue);
    gemm_kernel<<<dim3(32, 8), 256, GSMEM>>>();
    select_kernel<<<BQ, 256>>>(data, queue, jdx, out);
}

// round 10
// speedup vs baseline: 1.0614x; 1.0614x over previous
#include <cuda_runtime.h>
#include <cuda_bf16.h>
#include <cstdint>

#define BQ    1024
#define QMAX  32768
#define DIM   256
#define PERP  15
#define CANDMAX 256
#define DELTA 8.0f
#define QSCALE 20.0f            // int8 quant scale
#define INV_S2 (1.0f/200.0f)    // 2 / (QSCALE*QSCALE)
#define CAP   2048              // per-row candidate list capacity
#define TAU_Z 2.5f              // threshold: mean - 2.5 sigma (~200 pass / row)

// ---------------- scratch ----------------------------------------------------
__device__ __align__(16) int8_t g_q8[(size_t)QMAX * DIM];      // int8 mirror (8 MB)
__device__ float g_y2[QMAX];
__device__ unsigned long long g_cand[(size_t)BQ * CAP];        // 16 MB candidate lists
__device__ int   g_cnt[BQ];

// ---------------- prep: int8 quant + norms + cnt reset -----------------------
__global__ void __launch_bounds__(256) prep_kernel(const float* __restrict__ data,
                                                   const float* __restrict__ queue) {
    const int t    = threadIdx.x;
    const int row  = blockIdx.x * 4 + (t >> 6);
    const int l    = t & 63;
    const float* src = (row < BQ) ? (data + (size_t)row * DIM)
                                  : (queue + (size_t)(row - BQ) * DIM);
    float4 v = *(const float4*)(src + l * 4);

    int q0 = __float2int_rn(fminf(fmaxf(v.x * QSCALE, -127.f), 127.f));
    int q1 = __float2int_rn(fminf(fmaxf(v.y * QSCALE, -127.f), 127.f));
    int q2 = __float2int_rn(fminf(fmaxf(v.z * QSCALE, -127.f), 127.f));
    int q3 = __float2int_rn(fminf(fmaxf(v.w * QSCALE, -127.f), 127.f));
    uint32_t packed = (uint32_t)(q0 & 0xff) | ((uint32_t)(q1 & 0xff) << 8) |
                      ((uint32_t)(q2 & 0xff) << 16) | ((uint32_t)(q3 & 0xff) << 24);
    *(uint32_t*)(&g_q8[(size_t)row * DIM + l * 4]) = packed;

    float s = v.x*v.x + v.y*v.y + v.z*v.z + v.w*v.w;
    #pragma unroll
    for (int o = 16; o; o >>= 1) s += __shfl_xor_sync(0xffffffffu, s, o);
    __shared__ float ws[8];
    if ((t & 31) == 0) ws[t >> 5] = s;
    __syncthreads();
    if (l == 0) {
        g_y2[row] = ws[(t >> 6) * 2] + ws[(t >> 6) * 2 + 1];
        if (row < BQ) g_cnt[row] = 0;
    }
}

// ---------------- int8 IMMA GEMM: full-K prestaged, filtering epilogue -------
// CTA tile 128(M) x 128(N), K=256 in 4 chunk-stages of 64 for BOTH A and B
// (80 KB smem/CTA -> 2 CTAs/SM on 228 KB). Prologue issues all 4 chunks as
// separate commit groups; mainloop waits chunk kt (3-kt groups still pending),
// one __syncthreads per chunk. 8 warps as 2(m) x 4(n), warp tile 64x32.
#define BK      64
#define ROW_STR 80
#define STG     (128 * ROW_STR)              // 10240 per stage (A or B)
#define OFF_A   0                            // A stages 0..3
#define OFF_B   (4 * STG)                    // B stages 0..3
#define OFF_Y2  (8 * STG)                    // 81920
#define OFF_TAU (OFF_Y2 + 128 * 4)
#define GSMEM   (OFF_TAU + 128 * 4)          // 82944

__device__ __forceinline__ uint32_t smem_u32(const void* p) {
    uint32_t a;
    asm("{ .reg .u64 t; cvta.to.shared.u64 t, %1; cvt.u32.u64 %0, t; }" : "=r"(a) : "l"(p));
    return a;
}
#define CP_ASYNC16(dst, src) \
    asm volatile("cp.async.cg.shared.global [%0], [%1], 16;" :: "r"(dst), "l"(src))
#define CP_COMMIT() asm volatile("cp.async.commit_group;" ::: "memory")
#define CP_WAIT(n)  asm volatile("cp.async.wait_group %0;" :: "n"(n) : "memory")

__device__ __forceinline__ void ldsm_x4(uint32_t& r0, uint32_t& r1, uint32_t& r2,
                                        uint32_t& r3, uint32_t addr) {
    asm volatile("ldmatrix.sync.aligned.m8n8.x4.shared.b16 {%0,%1,%2,%3}, [%4];"
                 : "=r"(r0), "=r"(r1), "=r"(r2), "=r"(r3) : "r"(addr));
}
__device__ __forceinline__ void mma_s8(int c[4], uint32_t a0, uint32_t a1,
                                       uint32_t a2, uint32_t a3,
                                       uint32_t b0, uint32_t b1) {
    asm volatile(
        "mma.sync.aligned.m16n8k32.row.col.s32.s8.s8.s32 "
        "{%0,%1,%2,%3}, {%4,%5,%6,%7}, {%8,%9}, {%0,%1,%2,%3};\n"
        : "+r"(c[0]), "+r"(c[1]), "+r"(c[2]), "+r"(c[3])
        : "r"(a0), "r"(a1), "r"(a2), "r"(a3), "r"(b0), "r"(b1));
}
__device__ __forceinline__ unsigned long long make_key(float v, int j) {
    unsigned u = __float_as_uint(v);
    u = (u & 0x80000000u) ? ~u : (u | 0x80000000u);
    return ((unsigned long long)u << 32) | (unsigned)j;
}
__device__ __forceinline__ float key_val(unsigned long long k) {
    unsigned s = (unsigned)(k >> 32);
    unsigned u = (s & 0x80000000u) ? (s ^ 0x80000000u) : ~s;
    return __uint_as_float(u);
}
__device__ __forceinline__ void emit_cand(float v, int ri, int cj, float tau) {
    if (v < tau && cj != ri) {
        int p = atomicAdd(&g_cnt[ri], 1);
        if (p < CAP) g_cand[(size_t)ri * CAP + p] = make_key(v, cj);
    }
}

__global__ void __launch_bounds__(256, 2) gemm_kernel() {
    extern __shared__ __align__(16) char smem[];
    const uint32_t sb = smem_u32(smem);
    float* sy2  = (float*)(smem + OFF_Y2);
    float* stau = (float*)(smem + OFF_TAU);

    const int t    = threadIdx.x;
    const int lane = t & 31, wid = t >> 5;
    const int bm   = blockIdx.y * 128;
    const int bn   = blockIdx.x * 128;
    const int wm   = (wid >> 2) * 64;        // 0,64
    const int wn   = (wid & 3) * 32;         // 0..96
    const int gid  = lane >> 2, tig = lane & 3;

    // prologue: issue ALL 4 K-chunks of A and B (one commit group per chunk)
    #pragma unroll
    for (int kc = 0; kc < 4; kc++) {
        const uint32_t abuf = sb + OFF_A + kc * STG;
        const uint32_t bbuf = sb + OFF_B + kc * STG;
        #pragma unroll
        for (int i = t; i < 512; i += 256) {
            const int r = i >> 2, c = i & 3;
            CP_ASYNC16(abuf + (uint32_t)(r * ROW_STR + c * 16),
                       (const char*)&g_q8[(size_t)(bm + r) * DIM + kc * BK + c * 16]);
        }
        #pragma unroll
        for (int i = t; i < 512; i += 256) {
            const int r = i >> 2, c = i & 3;
            CP_ASYNC16(bbuf + (uint32_t)(r * ROW_STR + c * 16),
                       (const char*)&g_q8[(size_t)(bn + r) * DIM + kc * BK + c * 16]);
        }
        CP_COMMIT();
    }

    if (t < 32) *(float4*)&sy2[t * 4] = *(const float4*)&g_y2[bn + t * 4];
    if (t < 128) {
        const float x2 = g_y2[bm + t];
        stau[t] = 256.0f - TAU_Z * sqrtf(fmaf(4.0f, x2, 512.0f));
    }

    int acc[4][4][4];
    #pragma unroll
    for (int mi = 0; mi < 4; mi++)
        #pragma unroll
        for (int ni = 0; ni < 4; ni++)
            #pragma unroll
            for (int e = 0; e < 4; e++) acc[mi][ni][e] = 0;

    #pragma unroll
    for (int kt = 0; kt < 4; kt++) {
        switch (kt) {                          // chunk kt arrived; 3-kt still pending
            case 0: CP_WAIT(3); break;
            case 1: CP_WAIT(2); break;
            case 2: CP_WAIT(1); break;
            default: CP_WAIT(0); break;
        }
        __syncthreads();

        const uint32_t abuf = sb + OFF_A + kt * STG;
        const uint32_t bbuf = sb + OFF_B + kt * STG;
        #pragma unroll
        for (int kk = 0; kk < BK; kk += 32) {
            uint32_t a[4][4], b[4][2];
            const int acol = kk + ((lane >> 4) << 4);
            #pragma unroll
            for (int mi = 0; mi < 4; mi++) {
                const int ar = wm + mi * 16 + (lane & 15);
                ldsm_x4(a[mi][0], a[mi][1], a[mi][2], a[mi][3],
                        abuf + (uint32_t)(ar * ROW_STR + acol));
            }
            const int bcol = kk + (((lane >> 3) & 1) << 4);
            #pragma unroll
            for (int nj = 0; nj < 4; nj += 2) {
                const int br = wn + nj * 8 + (lane & 7) + ((lane >> 4) << 3);
                ldsm_x4(b[nj][0], b[nj][1], b[nj + 1][0], b[nj + 1][1],
                        bbuf + (uint32_t)(br * ROW_STR + bcol));
            }
            #pragma unroll
            for (int mi = 0; mi < 4; mi++)
                #pragma unroll
                for (int ni = 0; ni < 4; ni++)
                    mma_s8(acc[mi][ni], a[mi][0], a[mi][1], a[mi][2], a[mi][3],
                           b[ni][0], b[ni][1]);
        }
    }

    // filtering epilogue: emit v = y2 - 2*dot only when below per-row tau
    #pragma unroll
    for (int mi = 0; mi < 4; mi++) {
        const int lr = wm + mi * 16 + gid;
        const float tau0 = stau[lr], tau1 = stau[lr + 8];
        #pragma unroll
        for (int ni = 0; ni < 4; ni++) {
            const int lc = wn + ni * 8 + tig * 2;
            const float y0 = sy2[lc], y1 = sy2[lc + 1];
            emit_cand(fmaf(-INV_S2, (float)acc[mi][ni][0], y0), bm + lr,     bn + lc,     tau0);
            emit_cand(fmaf(-INV_S2, (float)acc[mi][ni][1], y1), bm + lr,     bn + lc + 1, tau0);
            emit_cand(fmaf(-INV_S2, (float)acc[mi][ni][2], y0), bm + lr + 8, bn + lc,     tau1);
            emit_cand(fmaf(-INV_S2, (float)acc[mi][ni][3], y1), bm + lr + 8, bn + lc + 1, tau1);
        }
    }
}

// ---------------- select: candidate list -> approx top-15 -> exact -----------
__global__ void __launch_bounds__(256) select_kernel(const float* __restrict__ data,
                                                     const float* __restrict__ queue,
                                                     const int* __restrict__ jdx,
                                                     float* __restrict__ out) {
    __shared__ unsigned long long skeys[256 * PERP];
    __shared__ unsigned long long swarp[8];
    __shared__ unsigned long long s_bcast;
    __shared__ unsigned long long sx[PERP];
    __shared__ __align__(16) float sdata[DIM];
    __shared__ int   cand[CANDMAX];
    __shared__ unsigned long long ckeys[CANDMAX];
    __shared__ int   s_cnt, s_nbr;

    const int row = blockIdx.x;
    const int t   = threadIdx.x;
    const int cnt0 = min(g_cnt[row], CAP);
    const unsigned long long* crow = g_cand + (size_t)row * CAP;

    if (t == 0) s_cnt = PERP;
    sdata[t] = data[(size_t)row * DIM + t];

    unsigned long long keys[PERP];
    #pragma unroll
    for (int i = 0; i < PERP; i++) keys[i] = ~0ULL;
    for (int j = t; j < cnt0; j += 256) {
        unsigned long long key = crow[j];
        if (key < keys[PERP - 1]) {
            #pragma unroll
            for (int i = PERP - 1; i >= 1; i--) {
                unsigned long long up = keys[i - 1];
                keys[i] = (key < up) ? up : ((key < keys[i]) ? key : keys[i]);
            }
            keys[0] = (key < keys[0]) ? key : keys[0];
        }
    }
    #pragma unroll
    for (int i = 0; i < PERP; i++) skeys[t * PERP + i] = keys[i];
    __syncthreads();

    for (int it = 0; it < PERP; it++) {
        unsigned long long m = ~0ULL;
        #pragma unroll
        for (int i = 0; i < PERP; i++) {
            unsigned long long v = skeys[t + i * 256];
            m = (v < m) ? v : m;
        }
        #pragma unroll
        for (int o = 16; o; o >>= 1) {
            unsigned long long other = __shfl_xor_sync(0xffffffffu, m, o);
            m = (other < m) ? other : m;
        }
        if ((t & 31) == 0) swarp[t >> 5] = m;
        __syncthreads();
        if (t == 0) {
            unsigned long long mm = swarp[0];
            #pragma unroll
            for (int i = 1; i < 8; i++) mm = (swarp[i] < mm) ? swarp[i] : mm;
            s_bcast = mm;
            sx[it]  = mm;
        }
        __syncthreads();
        unsigned long long cur = s_bcast;
        #pragma unroll
        for (int i = 0; i < PERP; i++) {
            int idx = t + i * 256;
            if (skeys[idx] == cur) skeys[idx] = ~0ULL;
        }
        __syncthreads();
    }

    const unsigned long long tkey = make_key(key_val(sx[PERP - 1]) + DELTA, 0);
    if (t < PERP) cand[t] = (int)(sx[t] & 0xffffffffu);
    #pragma unroll
    for (int i = 0; i < PERP; i++) {
        unsigned long long v = skeys[t + i * 256];
        if (v < tkey) {
            int p = atomicAdd(&s_cnt, 1);
            if (p < CANDMAX) cand[p] = (int)(v & 0xffffffffu);
        }
    }
    __syncthreads();
    const int cnt = (s_cnt < CANDMAX) ? s_cnt : CANDMAX;

    {
        const int lane = t & 31, wid = t >> 5;
        for (int c = wid; c < cnt; c += 8) {
            const int j = cand[c];
            const float* qj = (j < BQ) ? (data + (size_t)j * DIM)
                                       : (queue + (size_t)(j - BQ) * DIM);
            float4 x0 = *(const float4*)&sdata[lane * 8];
            float4 x1 = *(const float4*)&sdata[lane * 8 + 4];
            float4 y0 = *(const float4*)&qj[lane * 8];
            float4 y1 = *(const float4*)&qj[lane * 8 + 4];
            float d = x0.x*y0.x + x0.y*y0.y + x0.z*y0.z + x0.w*y0.w
                    + x1.x*y1.x + x1.y*y1.y + x1.z*y1.z + x1.w*y1.w;
            #pragma unroll
            for (int o = 16; o; o >>= 1) d += __shfl_xor_sync(0xffffffffu, d, o);
            if (lane == 0) ckeys[c] = make_key(fmaf(-2.0f, d, g_y2[j]), j);
        }
    }
    __syncthreads();

    const int r = jdx[row];
    if (t < cnt) {
        unsigned long long mykey = ckeys[t];
        int rank = 0;
        for (int d = 0; d < cnt; d++) rank += (ckeys[d] < mykey);
        if (rank == r) s_nbr = cand[t];
    }
    __syncthreads();
    const int nbr = s_nbr;
    const float* srow = (nbr < BQ) ? (data + (size_t)nbr * DIM)
                                   : (queue + (size_t)(nbr - BQ) * DIM);
    out[(size_t)row * DIM + t] = srow[t];
}

// ---------------- launch -----------------------------------------------------
extern "C" void kernel_launch(void* const* d_in, const int* in_sizes, int n_in,
                              void* d_out, int out_size) {
    (void)in_sizes; (void)n_in; (void)out_size;
    const float* data  = (const float*)d_in[0];
    const float* queue = (const float*)d_in[1];
    const int*   jdx   = (const int*)d_in[2];
    float*       out   = (float*)d_out;

    cudaFuncSetAttribute(gemm_kernel, cudaFuncAttributeMaxDynamicSharedMemorySize, GSMEM);

    prep_kernel<<<QMAX / 4, 256>>>(data, queue);
    gemm_kernel<<<dim3(QMAX / 128, BQ / 128), 256, GSMEM>>>();
    select_kernel<<<BQ, 256>>>(data, queue, jdx, out);
}